// round 11
// baseline (speedup 1.0000x reference)
#include <cuda_runtime.h>
#include <math.h>

#define NCTA 128
#define NTHR 512

// dynamic smem layout (float4 units), phase overlays:
//  GRU: buf0 @0, buf1 @5808; each buf: xE[64*33=2112], xD[2112]@+2112, w[48*33=1584]@+4224
//       red (3072 floats = 768 f4) @ 11616
//  ph3: buf0 @0, buf1 @2376; each: x[64*33=2112], w[8*33=264]@+2112
//  ph1: stoch[64*9=576] @0, Ws[8*9=72] @576
#define SMEM_F4 12384
#define SMEM_BYTES (SMEM_F4 * 16)   // 198144

typedef unsigned long long u64;
typedef ulonglong2 ull2;

__device__ __forceinline__ u64 fma2(u64 a, u64 b, u64 c) {
    u64 d;
    asm("fma.rn.f32x2 %0, %1, %2, %3;" : "=l"(d) : "l"(a), "l"(b), "l"(c));
    return d;
}
__device__ __forceinline__ float hsum(u64 v) {
    union { u64 u; float f[2]; } x; x.u = v;
    return x.f[0] + x.f[1];
}
__device__ __forceinline__ float sigm(float x) { return 1.f / (1.f + expf(-x)); }
__device__ __forceinline__ float softplusf(float x) {
    return fmaxf(x, 0.f) + log1pf(expf(-fabsf(x)));
}
__device__ __forceinline__ void cpa16(float4* dst, const void* src) {
    unsigned s = (unsigned)__cvta_generic_to_shared(dst);
    asm volatile("cp.async.cg.shared.global [%0], [%1], 16;" :: "r"(s), "l"(src));
}
#define CP_COMMIT() asm volatile("cp.async.commit_group;" ::: "memory")
#define CP_WAIT1()  asm volatile("cp.async.wait_group 1;" ::: "memory")
#define CP_WAIT0()  asm volatile("cp.async.wait_group 0;" ::: "memory")

// ---------------- persistent state ----------------
__device__ float g_emb[64 * 1024];
__device__ float g_det[2][64 * 1024];
__device__ float g_h1[64 * 512];
__device__ float g_hq[64 * 512];
__device__ float g_stoch[64 * 32];
__device__ float g_obsq[64 * 256 * 512];     // obs @ Wq1[:,1024:]^T + bq1
__device__ float g_actemb[64 * 256 * 1024];  // act @ Wsa[:,32:]^T + bsa
__device__ unsigned g_leaf[8][32];           // padded leaf counters
__device__ unsigned g_root;
__device__ volatile unsigned g_gen;

// two-level tree grid barrier; 128 co-resident CTAs (16 per leaf, 8 leaves)
__device__ __forceinline__ void gbar() {
    __syncthreads();
    if (threadIdx.x == 0) {
        __threadfence();
        unsigned gen = g_gen;
        int l = blockIdx.x & 7;
        if (atomicAdd(&g_leaf[l][0], 1u) == 15) {
            g_leaf[l][0] = 0;
            __threadfence();
            if (atomicAdd(&g_root, 1u) == 7) {
                g_root = 0;
                __threadfence();
                g_gen = gen + 1;
            }
        }
        while (g_gen == gen) { }
        __threadfence();
    }
    __syncthreads();
}

// ======== pre-pass A: g_obsq[r][c] = obs[r]·Wq1[c][1024:] + bq1[c] ========
__global__ void __launch_bounds__(256)
obsq_kernel(const float* __restrict__ obs, const float* __restrict__ Wq1,
            const float* __restrict__ bq1) {
    extern __shared__ float4 S[];
    const int tid = threadIdx.x, lane = tid & 31, wrp = tid >> 5;
    const int rt = blockIdx.x >> 2, ct = blockIdx.x & 3;
    const int r0 = rt * 64, c0 = ct * 128;
    const int rh = wrp >> 2, cgq = wrp & 3;

    u64 acc[32];
    #pragma unroll
    for (int j = 0; j < 32; ++j) acc[j] = 0ull;

    for (int c = 0; c < 16; ++c) {
        for (int i = tid; i < 1024; i += 256) {
            int row = i >> 4, k4 = i & 15;
            S[row * 17 + k4] = *(const float4*)(obs + (size_t)(r0 + row) * 1024 + c * 64 + k4 * 4);
        }
        for (int i = tid; i < 2048; i += 256) {
            int col = i >> 4, k4 = i & 15;
            S[1088 + col * 16 + k4] =
                *(const float4*)(Wq1 + (size_t)(c0 + col) * 2048 + 1024 + c * 64 + k4 * 4);
        }
        __syncthreads();
        const ull2* xr = (const ull2*)(S + (rh * 32 + lane) * 17);
        const ull2* wb = (const ull2*)(S + 1088 + (cgq * 32) * 16);
        for (int k4 = 0; k4 < 16; ++k4) {
            ull2 x = xr[k4];
            #pragma unroll
            for (int j = 0; j < 32; ++j) {
                ull2 w = wb[j * 16 + k4];
                acc[j] = fma2(w.x, x.x, acc[j]);
                acc[j] = fma2(w.y, x.y, acc[j]);
            }
        }
        __syncthreads();
    }
    int r = r0 + rh * 32 + lane;
    #pragma unroll
    for (int j = 0; j < 32; ++j) {
        int col = c0 + cgq * 32 + j;
        g_obsq[(size_t)r * 512 + col] = hsum(acc[j]) + bq1[col];
    }
}

// ======== pre-pass B: g_actemb[r][c] = act[r]·Wsa[c][32:] + bsa[c] ========
__global__ void __launch_bounds__(256)
actemb_kernel(const float* __restrict__ act, const float* __restrict__ Wsa,
              const float* __restrict__ bsa) {
    extern __shared__ float4 S[];           // x 64*17=1088, w 128*16=2048
    const int tid = threadIdx.x, lane = tid & 31, wrp = tid >> 5;
    const int rt = blockIdx.x >> 3, ct = blockIdx.x & 7;
    const int r0 = rt * 64, c0 = ct * 128;
    const int rh = wrp >> 2, cgq = wrp & 3;

    for (int i = tid; i < 1024; i += 256) {
        int row = i >> 4, k4 = i & 15;
        S[row * 17 + k4] = *(const float4*)(act + (size_t)(r0 + row) * 64 + k4 * 4);
    }
    for (int i = tid; i < 2048; i += 256) {
        int col = i >> 4, k4 = i & 15;
        S[1088 + col * 16 + k4] =
            *(const float4*)(Wsa + (size_t)(c0 + col) * 96 + 32 + k4 * 4);
    }
    __syncthreads();

    u64 acc[32];
    #pragma unroll
    for (int j = 0; j < 32; ++j) acc[j] = 0ull;
    const ull2* xr = (const ull2*)(S + (rh * 32 + lane) * 17);
    const ull2* wb = (const ull2*)(S + 1088 + (cgq * 32) * 16);
    for (int k4 = 0; k4 < 16; ++k4) {
        ull2 x = xr[k4];
        #pragma unroll
        for (int j = 0; j < 32; ++j) {
            ull2 w = wb[j * 16 + k4];
            acc[j] = fma2(w.x, x.x, acc[j]);
            acc[j] = fma2(w.y, x.y, acc[j]);
        }
    }
    int r = r0 + rh * 32 + lane;
    #pragma unroll
    for (int j = 0; j < 32; ++j) {
        int col = c0 + cgq * 32 + j;
        g_actemb[(size_t)r * 1024 + col] = hsum(acc[j]) + bsa[col];
    }
}

// ======== persistent rollout ========
__global__ void __launch_bounds__(NTHR, 1)
rssm_kernel(const float* __restrict__ obs,   const float* __restrict__ act,
            const float* __restrict__ nzp,   const float* __restrict__ nzq,
            const float* __restrict__ Wsa, const float* __restrict__ bsa,
            const float* __restrict__ Wih, const float* __restrict__ bih,
            const float* __restrict__ Whh, const float* __restrict__ bhh,
            const float* __restrict__ Wp1, const float* __restrict__ bp1,
            const float* __restrict__ Wp2, const float* __restrict__ bp2,
            const float* __restrict__ Wq1, const float* __restrict__ bq1,
            const float* __restrict__ Wq2, const float* __restrict__ bq2,
            float* __restrict__ out)
{
    extern __shared__ float4 S[];

    const int tid  = threadIdx.x;
    const int lane = tid & 31;
    const int wrp  = tid >> 5;
    const int c0g  = blockIdx.x * 8;

    // GRU tiling: h = K-split half; warp-tile = 16 rows x 4 cols (all 6 gatecols)
    const int h    = wrp >> 3;              // 0/1
    const int wq   = wrp & 7;
    const int rowg = wq & 3;                // 4 row groups of 16
    const int colg = wq >> 2;               // 2 col groups of 4
    const int tr   = lane & 7;
    const int tc   = lane >> 3;             // 0..3
    const int gr0  = rowg * 16 + tr;
    const int gr1  = gr0 + 8;
    const int gcol = colg * 4 + tc;         // 0..7 within CTA
    // ph1/ph3 tiling: thread = 1 output
    const int pr   = (wrp & 7) * 8 + tr;    // row 0..63
    const int pc   = (wrp >> 3) * 4 + tc;   // col 0..7

    for (int i = blockIdx.x * NTHR + tid; i < 64 * 1024; i += NCTA * NTHR)
        g_det[0][i] = 0.f;
    for (int i = blockIdx.x * NTHR + tid; i < 64 * 32; i += NCTA * NTHR)
        g_stoch[i] = 0.f;
    gbar();

    for (int t = 0; t < 256; ++t) {
        const int p = t & 1;
        const float* detP = g_det[p];
        float*       detN = g_det[p ^ 1];

        // ===== phase 1: emb = relu(stoch @ Ws^T + actemb), K=32 =====
        {
            float4* stS = S;            // 64 x 9
            float4* wS1 = S + 576;      // 8 x 9
            {
                int row = tid >> 3, k4 = tid & 7;
                cpa16(stS + row * 9 + k4, g_stoch + row * 32 + k4 * 4);
            }
            if (tid < 64) {
                int c = tid >> 3, k4 = tid & 7;
                cpa16(wS1 + c * 9 + k4, Wsa + (size_t)(c0g + c) * 96 + k4 * 4);
            }
            CP_COMMIT(); CP_WAIT0();
            __syncthreads();
            u64 a = 0;
            #pragma unroll
            for (int k4 = 0; k4 < 8; ++k4) {
                ull2 x = *(const ull2*)(stS + pr * 9 + k4);
                ull2 w = *(const ull2*)(wS1 + pc * 9 + k4);
                a = fma2(w.x, x.x, a); a = fma2(w.y, x.y, a);
            }
            int col = c0g + pc;
            float base = g_actemb[((size_t)pr * 256 + t) * 1024 + col];
            g_emb[(size_t)pr * 1024 + col] = fmaxf(hsum(a) + base, 0.f);
            __syncthreads();
        }
        gbar();

        // ===== phase 2: GRU, K chunks of 128, weights streamed =====
        {
            float4* b0 = S;
            float4* b1 = S + 5808;
            u64 acc[2][6];
            #pragma unroll
            for (int i = 0; i < 2; ++i)
                #pragma unroll
                for (int m = 0; m < 6; ++m) acc[i][m] = 0ull;

            auto stageG = [&](float4* buf, int j) {
                #pragma unroll
                for (int s = 0; s < 4; ++s) {
                    int idx = tid + s * 512;
                    int row = idx >> 5, k4 = idx & 31;
                    cpa16(buf + row * 33 + k4,
                          g_emb + (size_t)row * 1024 + j * 128 + k4 * 4);
                    cpa16(buf + 2112 + row * 33 + k4,
                          detP + (size_t)row * 1024 + j * 128 + k4 * 4);
                }
                #pragma unroll
                for (int s = 0; s < 3; ++s) {
                    int idx = tid + s * 512;
                    int gc = idx >> 5, k4 = idx & 31;
                    int cc = gc / 6, m = gc - cc * 6;
                    const float* srow = (m < 3)
                        ? (Wih + ((size_t)(c0g + cc) + 1024 * m) * 1024)
                        : (Whh + ((size_t)(c0g + cc) + 1024 * (m - 3)) * 1024);
                    cpa16(buf + 4224 + gc * 33 + k4, srow + j * 128 + k4 * 4);
                }
            };
            stageG(b0, 0); CP_COMMIT();
            stageG(b1, 1); CP_COMMIT();

            const int k0 = h * 16;
            for (int j = 0; j < 8; ++j) {
                if (j == 7) CP_WAIT0(); else CP_WAIT1();
                __syncthreads();
                const float4* buf = (j & 1) ? b1 : b0;
                const float4* xE = buf + gr0 * 33;
                const float4* xD = buf + 2112 + gr0 * 33;
                const float4* wp = buf + 4224 + (gcol * 6) * 33;
                #pragma unroll 4
                for (int k4 = k0; k4 < k0 + 16; ++k4) {
                    ull2 e0 = *(const ull2*)(xE + k4);
                    ull2 e1 = *(const ull2*)(xE + 264 + k4);
                    ull2 d0 = *(const ull2*)(xD + k4);
                    ull2 d1 = *(const ull2*)(xD + 264 + k4);
                    #pragma unroll
                    for (int m = 0; m < 3; ++m) {
                        ull2 w = *(const ull2*)(wp + m * 33 + k4);
                        acc[0][m] = fma2(w.x, e0.x, acc[0][m]);
                        acc[0][m] = fma2(w.y, e0.y, acc[0][m]);
                        acc[1][m] = fma2(w.x, e1.x, acc[1][m]);
                        acc[1][m] = fma2(w.y, e1.y, acc[1][m]);
                    }
                    #pragma unroll
                    for (int m = 3; m < 6; ++m) {
                        ull2 w = *(const ull2*)(wp + m * 33 + k4);
                        acc[0][m] = fma2(w.x, d0.x, acc[0][m]);
                        acc[0][m] = fma2(w.y, d0.y, acc[0][m]);
                        acc[1][m] = fma2(w.x, d1.x, acc[1][m]);
                        acc[1][m] = fma2(w.y, d1.y, acc[1][m]);
                    }
                }
                __syncthreads();
                if (j < 6) { stageG((j & 1) ? b1 : b0, j + 2); CP_COMMIT(); }
            }

            // cross-half reduction + gate math
            float* red = (float*)(S + 11616);   // [row][col 0..7][gate 0..5]
            if (h == 1) {
                #pragma unroll
                for (int r01 = 0; r01 < 2; ++r01) {
                    int row = r01 ? gr1 : gr0;
                    #pragma unroll
                    for (int m = 0; m < 6; ++m)
                        red[(row * 8 + gcol) * 6 + m] = hsum(acc[r01][m]);
                }
            }
            __syncthreads();
            if (h == 0) {
                const int col = c0g + gcol;
                #pragma unroll
                for (int r01 = 0; r01 < 2; ++r01) {
                    int row = r01 ? gr1 : gr0;
                    const float* rr = red + (row * 8 + gcol) * 6;
                    float ir = hsum(acc[r01][0]) + rr[0] + bih[col];
                    float iz = hsum(acc[r01][1]) + rr[1] + bih[col + 1024];
                    float in = hsum(acc[r01][2]) + rr[2] + bih[col + 2048];
                    float hr = hsum(acc[r01][3]) + rr[3] + bhh[col];
                    float hz = hsum(acc[r01][4]) + rr[4] + bhh[col + 1024];
                    float hn = hsum(acc[r01][5]) + rr[5] + bhh[col + 2048];
                    float r  = sigm(ir + hr);
                    float z  = sigm(iz + hz);
                    float n  = tanhf(in + r * hn);
                    float hp = detP[(size_t)row * 1024 + col];
                    float hw = (1.f - z) * n + z * hp;
                    detN[(size_t)row * 1024 + col] = hw;
                    out[((size_t)row * 256 + t) * 1216 + col] = hw;
                }
            }
            __syncthreads();
        }
        gbar();

        // ===== phase 3: h1 / hq first layers, K=1024, chunks of 128 =====
        {
            const bool isQ = blockIdx.x & 1;
            const int  c0  = (blockIdx.x >> 1) * 8;
            const float* W1 = isQ ? Wq1 : Wp1;
            const size_t K1 = isQ ? 2048 : 1024;
            float4* b0 = S;
            float4* b1 = S + 2376;
            u64 a = 0;

            auto stage3 = [&](float4* buf, int j) {
                #pragma unroll
                for (int s = 0; s < 4; ++s) {
                    int idx = tid + s * 512;
                    int row = idx >> 5, k4 = idx & 31;
                    cpa16(buf + row * 33 + k4,
                          detN + (size_t)row * 1024 + j * 128 + k4 * 4);
                }
                if (tid < 256) {
                    int c = tid >> 5, k4 = tid & 31;
                    cpa16(buf + 2112 + c * 33 + k4,
                          W1 + (size_t)(c0 + c) * K1 + j * 128 + k4 * 4);
                }
            };
            stage3(b0, 0); CP_COMMIT();
            stage3(b1, 1); CP_COMMIT();

            for (int j = 0; j < 8; ++j) {
                if (j == 7) CP_WAIT0(); else CP_WAIT1();
                __syncthreads();
                const float4* buf = (j & 1) ? b1 : b0;
                const float4* xp = buf + pr * 33;
                const float4* wp = buf + 2112 + pc * 33;
                #pragma unroll 8
                for (int k4 = 0; k4 < 32; ++k4) {
                    ull2 x = *(const ull2*)(xp + k4);
                    ull2 w = *(const ull2*)(wp + k4);
                    a = fma2(w.x, x.x, a); a = fma2(w.y, x.y, a);
                }
                __syncthreads();
                if (j < 6) { stage3((j & 1) ? b1 : b0, j + 2); CP_COMMIT(); }
            }

            const int col = c0 + pc;
            float base = isQ ? g_obsq[((size_t)pr * 256 + t) * 512 + col] : bp1[col];
            float v = fmaxf(hsum(a) + base, 0.f);
            (isQ ? g_hq : g_h1)[(size_t)pr * 512 + col] = v;
        }
        gbar();

        // ===== phase 4: second-layer heads, stochastic state =====
        {
            const int gw = blockIdx.x * 16 + wrp;       // 0..2047
            #pragma unroll
            for (int i = 0; i < 2; ++i) {
                int pi    = gw * 2 + i;                 // 0..4095
                int which = pi & 1;
                int s     = (pi >> 1) & 31;
                int bb    = pi >> 6;
                const float* hv = (which ? g_hq : g_h1) + (size_t)bb * 512;
                const float* W2 = which ? Wq2 : Wp2;
                u64 am = 0, asd = 0;
                #pragma unroll
                for (int q = 0; q < 4; ++q) {
                    float4 xf = __ldcg((const float4*)(hv + lane * 16 + q * 4));
                    ull2 x = *(ull2*)&xf;
                    ull2 u = *(const ull2*)(W2 + (size_t)s * 512 + lane * 16 + q * 4);
                    ull2 v = *(const ull2*)(W2 + (size_t)(s + 32) * 512 + lane * 16 + q * 4);
                    am  = fma2(u.x, x.x, am);  am  = fma2(u.y, x.y, am);
                    asd = fma2(v.x, x.x, asd); asd = fma2(v.y, x.y, asd);
                }
                float sm = hsum(am), ss = hsum(asd);
                #pragma unroll
                for (int o = 16; o; o >>= 1) {
                    sm += __shfl_xor_sync(0xffffffffu, sm, o);
                    ss += __shfl_xor_sync(0xffffffffu, ss, o);
                }
                if (lane == 0) {
                    const float* b2 = which ? bq2 : bp2;
                    float mean = sm + b2[s];
                    float stdv = softplusf(ss + b2[s + 32]) + 1e-5f;
                    const float* nz = which ? nzq : nzp;
                    float e  = nz[((size_t)bb * 256 + t) * 32 + s];
                    float st = mean + stdv * e;
                    size_t base = ((size_t)bb * 256 + t) * 1216 + 1024 + which * 96;
                    out[base + s]      = mean;
                    out[base + 32 + s] = stdv;
                    out[base + 64 + s] = st;
                    if (which) g_stoch[bb * 32 + s] = st;
                }
            }
        }
        gbar();
    }
}

extern "C" void kernel_launch(void* const* d_in, const int* in_sizes, int n_in,
                              void* d_out, int out_size) {
    (void)in_sizes; (void)n_in; (void)out_size;
    cudaFuncSetAttribute((const void*)obsq_kernel,
                         cudaFuncAttributeMaxDynamicSharedMemorySize, 50176);
    cudaFuncSetAttribute((const void*)actemb_kernel,
                         cudaFuncAttributeMaxDynamicSharedMemorySize, 50176);
    cudaFuncSetAttribute((const void*)rssm_kernel,
                         cudaFuncAttributeMaxDynamicSharedMemorySize, SMEM_BYTES);
    actemb_kernel<<<2048, 256, 50176>>>(
        (const float*)d_in[1], (const float*)d_in[4], (const float*)d_in[5]);
    obsq_kernel<<<1024, 256, 50176>>>(
        (const float*)d_in[0], (const float*)d_in[14], (const float*)d_in[15]);
    rssm_kernel<<<NCTA, NTHR, SMEM_BYTES>>>(
        (const float*)d_in[0],  (const float*)d_in[1],
        (const float*)d_in[2],  (const float*)d_in[3],
        (const float*)d_in[4],  (const float*)d_in[5],
        (const float*)d_in[6],  (const float*)d_in[7],
        (const float*)d_in[8],  (const float*)d_in[9],
        (const float*)d_in[10], (const float*)d_in[11],
        (const float*)d_in[12], (const float*)d_in[13],
        (const float*)d_in[14], (const float*)d_in[15],
        (const float*)d_in[16], (const float*)d_in[17],
        (float*)d_out);
}

// round 12
// speedup vs baseline: 1.1089x; 1.1089x over previous
#include <cuda_runtime.h>
#include <math.h>

#define NCTA 128
#define NTHR 512
#define WG_F4 12336
#define SMEM_F4 (WG_F4 + 2048)
#define SMEM_BYTES (SMEM_F4 * 16)   // 230144

typedef unsigned long long u64;
typedef ulonglong2 ull2;

__device__ __forceinline__ u64 fma2(u64 a, u64 b, u64 c) {
    u64 d;
    asm("fma.rn.f32x2 %0, %1, %2, %3;" : "=l"(d) : "l"(a), "l"(b), "l"(c));
    return d;
}
__device__ __forceinline__ float hsum(u64 v) {
    union { u64 u; float f[2]; } x; x.u = v;
    return x.f[0] + x.f[1];
}
__device__ __forceinline__ float sigm(float x) { return 1.f / (1.f + expf(-x)); }
__device__ __forceinline__ float softplusf(float x) {
    return fmaxf(x, 0.f) + log1pf(expf(-fabsf(x)));
}

// ---------------- persistent state ----------------
__device__ float g_emb[64 * 1024];
__device__ float g_det[2][64 * 1024];
__device__ float g_h1[64 * 512];
__device__ float g_hq[64 * 512];
__device__ float g_stoch[64 * 32];
__device__ float g_obsq[64 * 256 * 512];     // obs @ Wq1[:,1024:]^T + bq1
__device__ float g_actemb[64 * 256 * 1024];  // act @ Wsa[:,32:]^T + bsa
__device__ unsigned g_leaf[8][32];
__device__ unsigned g_root;
__device__ volatile unsigned g_gen;

__device__ __forceinline__ void gbar() {
    __syncthreads();
    if (threadIdx.x == 0) {
        __threadfence();
        unsigned gen = g_gen;
        int l = blockIdx.x & 7;
        if (atomicAdd(&g_leaf[l][0], 1u) == 15) {
            g_leaf[l][0] = 0;
            __threadfence();
            if (atomicAdd(&g_root, 1u) == 7) {
                g_root = 0;
                __threadfence();
                g_gen = gen + 1;
            }
        }
        while (g_gen == gen) { }
        __threadfence();
    }
    __syncthreads();
}

// ======== pre-pass A: g_obsq ========
__global__ void __launch_bounds__(256)
obsq_kernel(const float* __restrict__ obs, const float* __restrict__ Wq1,
            const float* __restrict__ bq1) {
    extern __shared__ float4 S[];
    const int tid = threadIdx.x, lane = tid & 31, wrp = tid >> 5;
    const int rt = blockIdx.x >> 2, ct = blockIdx.x & 3;
    const int r0 = rt * 64, c0 = ct * 128;
    const int rh = wrp >> 2, cgq = wrp & 3;

    u64 acc[32];
    #pragma unroll
    for (int j = 0; j < 32; ++j) acc[j] = 0ull;

    for (int c = 0; c < 16; ++c) {
        for (int i = tid; i < 1024; i += 256) {
            int row = i >> 4, k4 = i & 15;
            S[row * 17 + k4] = *(const float4*)(obs + (size_t)(r0 + row) * 1024 + c * 64 + k4 * 4);
        }
        for (int i = tid; i < 2048; i += 256) {
            int col = i >> 4, k4 = i & 15;
            S[1088 + col * 16 + k4] =
                *(const float4*)(Wq1 + (size_t)(c0 + col) * 2048 + 1024 + c * 64 + k4 * 4);
        }
        __syncthreads();
        const ull2* xr = (const ull2*)(S + (rh * 32 + lane) * 17);
        const ull2* wb = (const ull2*)(S + 1088 + (cgq * 32) * 16);
        for (int k4 = 0; k4 < 16; ++k4) {
            ull2 x = xr[k4];
            #pragma unroll
            for (int j = 0; j < 32; ++j) {
                ull2 w = wb[j * 16 + k4];
                acc[j] = fma2(w.x, x.x, acc[j]);
                acc[j] = fma2(w.y, x.y, acc[j]);
            }
        }
        __syncthreads();
    }
    int r = r0 + rh * 32 + lane;
    #pragma unroll
    for (int j = 0; j < 32; ++j) {
        int col = c0 + cgq * 32 + j;
        g_obsq[(size_t)r * 512 + col] = hsum(acc[j]) + bq1[col];
    }
}

// ======== pre-pass B: g_actemb ========
__global__ void __launch_bounds__(256)
actemb_kernel(const float* __restrict__ act, const float* __restrict__ Wsa,
              const float* __restrict__ bsa) {
    extern __shared__ float4 S[];
    const int tid = threadIdx.x, lane = tid & 31, wrp = tid >> 5;
    const int rt = blockIdx.x >> 3, ct = blockIdx.x & 7;
    const int r0 = rt * 64, c0 = ct * 128;
    const int rh = wrp >> 2, cgq = wrp & 3;

    for (int i = tid; i < 1024; i += 256) {
        int row = i >> 4, k4 = i & 15;
        S[row * 17 + k4] = *(const float4*)(act + (size_t)(r0 + row) * 64 + k4 * 4);
    }
    for (int i = tid; i < 2048; i += 256) {
        int col = i >> 4, k4 = i & 15;
        S[1088 + col * 16 + k4] =
            *(const float4*)(Wsa + (size_t)(c0 + col) * 96 + 32 + k4 * 4);
    }
    __syncthreads();

    u64 acc[32];
    #pragma unroll
    for (int j = 0; j < 32; ++j) acc[j] = 0ull;
    const ull2* xr = (const ull2*)(S + (rh * 32 + lane) * 17);
    const ull2* wb = (const ull2*)(S + 1088 + (cgq * 32) * 16);
    for (int k4 = 0; k4 < 16; ++k4) {
        ull2 x = xr[k4];
        #pragma unroll
        for (int j = 0; j < 32; ++j) {
            ull2 w = wb[j * 16 + k4];
            acc[j] = fma2(w.x, x.x, acc[j]);
            acc[j] = fma2(w.y, x.y, acc[j]);
        }
    }
    int r = r0 + rh * 32 + lane;
    #pragma unroll
    for (int j = 0; j < 32; ++j) {
        int col = c0 + cgq * 32 + j;
        g_actemb[(size_t)r * 1024 + col] = hsum(acc[j]) + bsa[col];
    }
}

// ======== persistent rollout ========
__global__ void __launch_bounds__(NTHR, 1)
rssm_kernel(const float* __restrict__ obs,   const float* __restrict__ act,
            const float* __restrict__ nzp,   const float* __restrict__ nzq,
            const float* __restrict__ Wsa, const float* __restrict__ bsa,
            const float* __restrict__ Wih, const float* __restrict__ bih,
            const float* __restrict__ Whh, const float* __restrict__ bhh,
            const float* __restrict__ Wp1, const float* __restrict__ bp1,
            const float* __restrict__ Wp2, const float* __restrict__ bp2,
            const float* __restrict__ Wq1, const float* __restrict__ bq1,
            const float* __restrict__ Wq2, const float* __restrict__ bq2,
            float* __restrict__ out)
{
    extern __shared__ float4 S[];
    float4* wG = S;                   // 48 gatecols x 257
    float4* xb = S + WG_F4;           // 2048 f4 overlay region

    const int tid  = threadIdx.x;
    const int lane = tid & 31;
    const int wrp  = tid >> 5;
    const int c0g  = blockIdx.x * 8;
    const int r0   = lane & 7;
    const int cq   = lane >> 3;       // 0..3

    // GRU ids: 16 warps = h(4 K-split) x gp(2 oc-groups) x mat(2)
    const int h    = wrp & 3;
    const int gp   = (wrp >> 2) & 1;
    const int mat  = wrp >> 3;        // 0: i-gates (x=emb), 1: h-gates (x=det)
    const int oc   = gp * 4 + cq;     // 0..7
    // ph1/ph3 ids
    const int pr   = (wrp & 7) * 8 + r0;
    const int pc   = (wrp >> 3) * 4 + cq;
    const int h3   = wrp & 7;         // ph3 K-split 8
    const int rw3  = wrp >> 3;        // ph3 row half

    // ---- init: zero state, load GRU weight slice (once) ----
    for (int i = blockIdx.x * NTHR + tid; i < 64 * 1024; i += NCTA * NTHR)
        g_det[0][i] = 0.f;
    for (int i = blockIdx.x * NTHR + tid; i < 64 * 32; i += NCTA * NTHR)
        g_stoch[i] = 0.f;
    for (int i = tid; i < WG_F4; i += NTHR) {
        int gc = i / 257, k = i - gc * 257;
        if (k < 256) {
            int col = gc / 6, g = gc - col * 6;
            const float* srow = (g < 3)
                ? (Wih + ((size_t)(c0g + col) + 1024 * g) * 1024)
                : (Whh + ((size_t)(c0g + col) + 1024 * (g - 3)) * 1024);
            wG[i] = *(const float4*)(srow + k * 4);
        }
    }
    gbar();

    // GRU per-thread weight bases (gc = oc*6 + mat*3 + m)
    const float4* wgm0 = wG + (oc * 6 + mat * 3 + 0) * 257;
    const float4* wgm1 = wG + (oc * 6 + mat * 3 + 1) * 257;
    const float4* wgm2 = wG + (oc * 6 + mat * 3 + 2) * 257;
    const int k4a = h * 2, k4b = h * 2 + 1;
    const int xoa = r0 * 8 + (k4a ^ r0);
    const int xob = r0 * 8 + (k4b ^ r0);

    // GRU prefetch mapping (2 slots per thread)
    const int pi0 = tid * 2, pi1 = tid * 2 + 1;
    const int pm0 = pi0 >> 9, prw0 = (pi0 >> 3) & 63, pk0 = pi0 & 7;
    const int pm1 = pi1 >> 9, prw1 = (pi1 >> 3) & 63, pk1 = pi1 & 7;
    const int pd0 = pm0 * 512 + prw0 * 8 + (pk0 ^ (prw0 & 7));
    const int pd1 = pm1 * 512 + prw1 * 8 + (pk1 ^ (prw1 & 7));

    for (int t = 0; t < 256; ++t) {
        const int p = t & 1;
        const float* detP = g_det[p];
        float*       detN = g_det[p ^ 1];

        // ===== phase 1: emb = relu(stoch @ Ws^T + actemb), K=32 =====
        {
            float4* stS = xb;           // 64 x 9
            float4* wS1 = xb + 576;     // 8 x 9
            {
                int row = tid >> 3, k4 = tid & 7;
                stS[row * 9 + k4] = *(const float4*)(g_stoch + row * 32 + k4 * 4);
            }
            if (tid < 64) {
                int c = tid >> 3, k4 = tid & 7;
                wS1[c * 9 + k4] = *(const float4*)(Wsa + (size_t)(c0g + c) * 96 + k4 * 4);
            }
            __syncthreads();
            u64 a = 0;
            #pragma unroll
            for (int k4 = 0; k4 < 8; ++k4) {
                ull2 x = *(const ull2*)(stS + pr * 9 + k4);
                ull2 w = *(const ull2*)(wS1 + pc * 9 + k4);
                a = fma2(w.x, x.x, a); a = fma2(w.y, x.y, a);
            }
            int col = c0g + pc;
            float base = g_actemb[((size_t)pr * 256 + t) * 1024 + col];
            g_emb[(size_t)pr * 1024 + col] = fmaxf(hsum(a) + base, 0.f);
        }
        gbar();

        // ===== phase 2: GRU =====
        {
            float4* b0 = xb;
            float4* b1 = xb + 1024;
            const float* ps0 = (pm0 ? detP : g_emb) + prw0 * 1024 + pk0 * 4;
            const float* ps1 = (pm1 ? detP : g_emb) + prw1 * 1024 + pk1 * 4;

            u64 acc[24];
            #pragma unroll
            for (int n = 0; n < 24; ++n) acc[n] = 0ull;

            b0[pd0] = *(const float4*)(ps0);
            b0[pd1] = *(const float4*)(ps1);
            __syncthreads();

            for (int j = 0; j < 32; ++j) {
                float4 pf0, pf1;
                if (j < 31) {
                    pf0 = *(const float4*)(ps0 + (j + 1) * 32);
                    pf1 = *(const float4*)(ps1 + (j + 1) * 32);
                }
                const float4* buf = (j & 1) ? b1 : b0;
                const float4* xm  = buf + mat * 512;
                ull2 wa0 = *(const ull2*)(wgm0 + j * 8 + k4a);
                ull2 wb0 = *(const ull2*)(wgm1 + j * 8 + k4a);
                ull2 wc0 = *(const ull2*)(wgm2 + j * 8 + k4a);
                ull2 wa1 = *(const ull2*)(wgm0 + j * 8 + k4b);
                ull2 wb1 = *(const ull2*)(wgm1 + j * 8 + k4b);
                ull2 wc1 = *(const ull2*)(wgm2 + j * 8 + k4b);
                #pragma unroll
                for (int i = 0; i < 8; ++i) {
                    ull2 x = *(const ull2*)(xm + xoa + 64 * i);
                    acc[i*3+0] = fma2(wa0.x, x.x, acc[i*3+0]);
                    acc[i*3+0] = fma2(wa0.y, x.y, acc[i*3+0]);
                    acc[i*3+1] = fma2(wb0.x, x.x, acc[i*3+1]);
                    acc[i*3+1] = fma2(wb0.y, x.y, acc[i*3+1]);
                    acc[i*3+2] = fma2(wc0.x, x.x, acc[i*3+2]);
                    acc[i*3+2] = fma2(wc0.y, x.y, acc[i*3+2]);
                }
                #pragma unroll
                for (int i = 0; i < 8; ++i) {
                    ull2 x = *(const ull2*)(xm + xob + 64 * i);
                    acc[i*3+0] = fma2(wa1.x, x.x, acc[i*3+0]);
                    acc[i*3+0] = fma2(wa1.y, x.y, acc[i*3+0]);
                    acc[i*3+1] = fma2(wb1.x, x.x, acc[i*3+1]);
                    acc[i*3+1] = fma2(wb1.y, x.y, acc[i*3+1]);
                    acc[i*3+2] = fma2(wc1.x, x.x, acc[i*3+2]);
                    acc[i*3+2] = fma2(wc1.y, x.y, acc[i*3+2]);
                }
                if (j < 31) {
                    float4* nb = (j & 1) ? b0 : b1;
                    nb[pd0] = pf0;
                    nb[pd1] = pf1;
                }
                __syncthreads();
            }

            float f[24];
            #pragma unroll
            for (int n = 0; n < 24; ++n) f[n] = hsum(acc[n]);
            float* R = (float*)xb;

            if (h >= 2) {
                float* pp = R + (((h - 2) * 4 + gp * 2 + mat) * 32 + lane) * 24;
                #pragma unroll
                for (int n = 0; n < 24; ++n) pp[n] = f[n];
            }
            __syncthreads();
            if (h < 2) {
                const float* pp = R + ((h * 4 + gp * 2 + mat) * 32 + lane) * 24;
                #pragma unroll
                for (int n = 0; n < 24; ++n) f[n] += pp[n];
            }
            __syncthreads();
            if (h == 1) {
                float* pp = R + ((gp * 2 + mat) * 32 + lane) * 24;
                #pragma unroll
                for (int n = 0; n < 24; ++n) pp[n] = f[n];
            }
            __syncthreads();
            if (h == 0) {
                const float* pp = R + ((gp * 2 + mat) * 32 + lane) * 24;
                #pragma unroll
                for (int n = 0; n < 24; ++n) f[n] += pp[n];
            }
            __syncthreads();
            if (h == 0 && mat == 1) {
                int col = c0g + oc;
                float* pp = R + (gp * 32 + lane) * 24;
                #pragma unroll
                for (int i = 0; i < 8; ++i)
                    #pragma unroll
                    for (int m = 0; m < 3; ++m)
                        pp[i * 3 + m] = f[i * 3 + m] + bhh[col + 1024 * m];
            }
            __syncthreads();
            if (h == 0 && mat == 0) {
                int col = c0g + oc;
                const float* ph = R + (gp * 32 + lane) * 24;
                #pragma unroll
                for (int i = 0; i < 8; ++i) {
                    int row = r0 + 8 * i;
                    float ir = f[i*3+0] + bih[col];
                    float iz = f[i*3+1] + bih[col + 1024];
                    float in = f[i*3+2] + bih[col + 2048];
                    float hr = ph[i*3+0], hz = ph[i*3+1], hn = ph[i*3+2];
                    float r  = sigm(ir + hr);
                    float z  = sigm(iz + hz);
                    float n  = tanhf(in + r * hn);
                    float hp = detP[(size_t)row * 1024 + col];
                    float hw = (1.f - z) * n + z * hp;
                    detN[(size_t)row * 1024 + col] = hw;
                    out[((size_t)row * 256 + t) * 1216 + col] = hw;
                }
            }
        }
        gbar();

        // ===== phase 3: h1 / hq first layers (K=1024; obs part precomputed) =====
        {
            const bool isQ = blockIdx.x & 1;
            const int  c0  = (blockIdx.x >> 1) * 8;
            const float* W1 = isQ ? Wq1 : Wp1;
            const size_t K1 = isQ ? 2048 : 1024;
            float4* b0 = xb;
            float4* b1 = xb + 584;

            const int xrow = tid >> 3, xk4 = tid & 7;
            const float* xsrc = detN + (size_t)xrow * 1024 + xk4 * 4;
            const int xdst = xrow * 8 + (xk4 ^ (xrow & 7));
            const float* wsrc = W1;
            int wdst = 0;
            if (tid < 64) {
                int wc = tid >> 3, wk = tid & 7;
                wsrc = W1 + (size_t)(c0 + wc) * K1 + wk * 4;
                wdst = 512 + wc * 9 + wk;
            }

            u64 acc[8];
            #pragma unroll
            for (int n = 0; n < 8; ++n) acc[n] = 0ull;

            b0[xdst] = *(const float4*)(xsrc);
            if (tid < 64) b0[wdst] = *(const float4*)(wsrc);
            __syncthreads();

            const int xbase = (rw3 * 32 + r0) * 8 + (h3 ^ r0);
            for (int j = 0; j < 32; ++j) {
                float4 pfx, pfw;
                if (j < 31) {
                    pfx = *(const float4*)(xsrc + (j + 1) * 32);
                    if (tid < 64) pfw = *(const float4*)(wsrc + (j + 1) * 32);
                }
                const float4* buf = (j & 1) ? b1 : b0;
                ull2 w0 = *(const ull2*)(buf + 512 + (cq * 2) * 9 + h3);
                ull2 w1 = *(const ull2*)(buf + 512 + (cq * 2 + 1) * 9 + h3);
                #pragma unroll
                for (int i = 0; i < 4; ++i) {
                    ull2 x = *(const ull2*)(buf + xbase + 64 * i);
                    acc[i*2+0] = fma2(w0.x, x.x, acc[i*2+0]);
                    acc[i*2+0] = fma2(w0.y, x.y, acc[i*2+0]);
                    acc[i*2+1] = fma2(w1.x, x.x, acc[i*2+1]);
                    acc[i*2+1] = fma2(w1.y, x.y, acc[i*2+1]);
                }
                if (j < 31) {
                    float4* nb = (j & 1) ? b0 : b1;
                    nb[xdst] = pfx;
                    if (tid < 64) nb[wdst] = pfw;
                }
                __syncthreads();
            }

            float f[8];
            #pragma unroll
            for (int n = 0; n < 8; ++n) f[n] = hsum(acc[n]);
            float* Rf = (float*)xb;
            if (h3 > 0) {
                float* pp = Rf + (((h3 - 1) * 2 + rw3) * 32 + lane) * 8;
                #pragma unroll
                for (int n = 0; n < 8; ++n) pp[n] = f[n];
            }
            __syncthreads();
            if (h3 == 0) {
                for (int s = 0; s < 7; ++s) {
                    const float* pp = Rf + ((s * 2 + rw3) * 32 + lane) * 8;
                    #pragma unroll
                    for (int n = 0; n < 8; ++n) f[n] += pp[n];
                }
                float* dst = isQ ? g_hq : g_h1;
                #pragma unroll
                for (int i = 0; i < 4; ++i) {
                    int row = rw3 * 32 + r0 + 8 * i;
                    #pragma unroll
                    for (int c = 0; c < 2; ++c) {
                        int col = c0 + cq * 2 + c;
                        float base = isQ ? g_obsq[((size_t)row * 256 + t) * 512 + col]
                                         : bp1[col];
                        dst[(size_t)row * 512 + col] = fmaxf(f[i*2+c] + base, 0.f);
                    }
                }
            }
        }
        gbar();

        // ===== phase 4: heads =====
        {
            const int gw = blockIdx.x * 16 + wrp;
            #pragma unroll
            for (int i = 0; i < 2; ++i) {
                int pi    = gw * 2 + i;
                int which = pi & 1;
                int s     = (pi >> 1) & 31;
                int bb    = pi >> 6;
                const float* hv = (which ? g_hq : g_h1) + (size_t)bb * 512;
                const float* W2 = which ? Wq2 : Wp2;
                u64 am = 0, asd = 0;
                #pragma unroll
                for (int q = 0; q < 4; ++q) {
                    float4 xf = __ldcg((const float4*)(hv + lane * 16 + q * 4));
                    ull2 x = *(ull2*)&xf;
                    ull2 u = *(const ull2*)(W2 + (size_t)s * 512 + lane * 16 + q * 4);
                    ull2 v = *(const ull2*)(W2 + (size_t)(s + 32) * 512 + lane * 16 + q * 4);
                    am  = fma2(u.x, x.x, am);  am  = fma2(u.y, x.y, am);
                    asd = fma2(v.x, x.x, asd); asd = fma2(v.y, x.y, asd);
                }
                float sm = hsum(am), ss = hsum(asd);
                #pragma unroll
                for (int o = 16; o; o >>= 1) {
                    sm += __shfl_xor_sync(0xffffffffu, sm, o);
                    ss += __shfl_xor_sync(0xffffffffu, ss, o);
                }
                if (lane == 0) {
                    const float* b2 = which ? bq2 : bp2;
                    float mean = sm + b2[s];
                    float stdv = softplusf(ss + b2[s + 32]) + 1e-5f;
                    const float* nz = which ? nzq : nzp;
                    float e  = nz[((size_t)bb * 256 + t) * 32 + s];
                    float st = mean + stdv * e;
                    size_t base = ((size_t)bb * 256 + t) * 1216 + 1024 + which * 96;
                    out[base + s]      = mean;
                    out[base + 32 + s] = stdv;
                    out[base + 64 + s] = st;
                    if (which) g_stoch[bb * 32 + s] = st;
                }
            }
        }
        gbar();
    }
}

extern "C" void kernel_launch(void* const* d_in, const int* in_sizes, int n_in,
                              void* d_out, int out_size) {
    (void)in_sizes; (void)n_in; (void)out_size;
    cudaFuncSetAttribute((const void*)obsq_kernel,
                         cudaFuncAttributeMaxDynamicSharedMemorySize, 50176);
    cudaFuncSetAttribute((const void*)actemb_kernel,
                         cudaFuncAttributeMaxDynamicSharedMemorySize, 50176);
    cudaFuncSetAttribute((const void*)rssm_kernel,
                         cudaFuncAttributeMaxDynamicSharedMemorySize, SMEM_BYTES);
    actemb_kernel<<<2048, 256, 50176>>>(
        (const float*)d_in[1], (const float*)d_in[4], (const float*)d_in[5]);
    obsq_kernel<<<1024, 256, 50176>>>(
        (const float*)d_in[0], (const float*)d_in[14], (const float*)d_in[15]);
    rssm_kernel<<<NCTA, NTHR, SMEM_BYTES>>>(
        (const float*)d_in[0],  (const float*)d_in[1],
        (const float*)d_in[2],  (const float*)d_in[3],
        (const float*)d_in[4],  (const float*)d_in[5],
        (const float*)d_in[6],  (const float*)d_in[7],
        (const float*)d_in[8],  (const float*)d_in[9],
        (const float*)d_in[10], (const float*)d_in[11],
        (const float*)d_in[12], (const float*)d_in[13],
        (const float*)d_in[14], (const float*)d_in[15],
        (const float*)d_in[16], (const float*)d_in[17],
        (float*)d_out);
}